// round 17
// baseline (speedup 1.0000x reference)
#include <cuda_runtime.h>
#include <math_constants.h>

#define N_NODES 8192
#define F 512
#define ALPHA 0.2f
#define NPART 128          // stage-1 partial blocks (4 o-rows each)

// Scratch (no dynamic allocation allowed)
__device__ __align__(16) float g_part1[NPART * F];
__device__ __align__(16) float g_part2[NPART * F];
__device__ __align__(16) float g_w1[F];
__device__ __align__(16) float g_w2[F];
__device__ __align__(16) float g_s1[N_NODES];
__device__ __align__(16) float g_s2[N_NODES];
__device__ unsigned int g_s2max_u;   // monotone-encoded float max

// Monotone encoding: preserves float ordering under unsigned compare.
__device__ __forceinline__ unsigned int enc_f32(float x) {
    unsigned int b = __float_as_uint(x);
    return (b & 0x80000000u) ? ~b : (b | 0x80000000u);
}
__device__ __forceinline__ float dec_f32(unsigned int u) {
    return (u & 0x80000000u) ? __uint_as_float(u & 0x7fffffffu)
                             : __uint_as_float(~u);
}

// ---------------------------------------------------------------------------
// Stage 1: partial fold of attention vector through W.
// Also resets g_s2max_u for this launch (runs first in stream every call).
// ---------------------------------------------------------------------------
__global__ void wvec_part_kernel(const float* __restrict__ W,
                                 const float* __restrict__ a) {
    const int b = blockIdx.x;
    const int t = threadIdx.x;            // 0..255
    if (b == 0 && t == 0) g_s2max_u = 0u; // encoded sentinel below all reals
    const int o0 = b * 4;
    float acc1a = 0.f, acc2a = 0.f;       // for k = t
    float acc1b = 0.f, acc2b = 0.f;       // for k = t + 256
    #pragma unroll
    for (int j = 0; j < 4; j++) {
        const int o = o0 + j;
        const float a1 = a[o];
        const float a2 = a[F + o];
        const float wa = W[o * F + t];
        const float wb = W[o * F + t + 256];
        acc1a = fmaf(wa, a1, acc1a);
        acc2a = fmaf(wa, a2, acc2a);
        acc1b = fmaf(wb, a1, acc1b);
        acc2b = fmaf(wb, a2, acc2b);
    }
    g_part1[b * F + t]       = acc1a;
    g_part1[b * F + t + 256] = acc1b;
    g_part2[b * F + t]       = acc2a;
    g_part2[b * F + t + 256] = acc2b;
}

// ---------------------------------------------------------------------------
// Stage 2: reduce NPART partials per k. 2 CTAs x 1024 threads; 4 threads per
// k, each sums 32 partials, combined with two shfl steps. Deterministic.
// ---------------------------------------------------------------------------
__global__ void wvec_reduce_kernel() {
    const int gt = blockIdx.x * 1024 + threadIdx.x;  // 0..2047
    const int k = gt >> 2;            // 0..511
    const int q = gt & 3;             // quarter of the b range
    const int b0 = q * (NPART / 4);
    float s1 = 0.f, s2 = 0.f;
    #pragma unroll 8
    for (int j = 0; j < NPART / 4; j++) {
        s1 += g_part1[(b0 + j) * F + k];
        s2 += g_part2[(b0 + j) * F + k];
    }
    // combine the 4 q-lanes (adjacent lanes within the warp)
    s1 += __shfl_xor_sync(0xffffffffu, s1, 1);
    s2 += __shfl_xor_sync(0xffffffffu, s2, 1);
    s1 += __shfl_xor_sync(0xffffffffu, s1, 2);
    s2 += __shfl_xor_sync(0xffffffffu, s2, 2);
    if (q == 0) {
        g_w1[k] = s1;
        g_w2[k] = s2;
    }
}

// ---------------------------------------------------------------------------
// Per-node scores. One warp per node row. Also folds the global max of s2
// via one order-invariant atomicMax per CTA (exact + deterministic).
// ---------------------------------------------------------------------------
__global__ void sdot_kernel(const float* __restrict__ nodes) {
    int warp = (blockIdx.x * blockDim.x + threadIdx.x) >> 5;
    int lane = threadIdx.x & 31;
    int wid  = threadIdx.x >> 5;
    const float4* nrow = (const float4*)(nodes + (size_t)warp * F);
    const float4* w1v  = (const float4*)g_w1;
    const float4* w2v  = (const float4*)g_w2;
    float a1 = 0.f, a2 = 0.f;
    #pragma unroll
    for (int i = 0; i < 4; i++) {
        int idx = lane + i * 32;
        float4 v = nrow[idx];
        float4 x = w1v[idx];
        float4 y = w2v[idx];
        a1 += v.x * x.x + v.y * x.y + v.z * x.z + v.w * x.w;
        a2 += v.x * y.x + v.y * y.y + v.z * y.z + v.w * y.w;
    }
    #pragma unroll
    for (int off = 16; off; off >>= 1) {
        a1 += __shfl_xor_sync(0xffffffffu, a1, off);
        a2 += __shfl_xor_sync(0xffffffffu, a2, off);
    }
    __shared__ float sm[8];
    if (lane == 0) {
        g_s1[warp] = a1;
        g_s2[warp] = a2;
        sm[wid] = a2;
    }
    __syncthreads();
    if (threadIdx.x == 0) {
        float m = sm[0];
        #pragma unroll
        for (int w = 1; w < 8; w++) m = fmaxf(m, sm[w]);
        atomicMax(&g_s2max_u, enc_f32(m));
    }
}

// ---------------------------------------------------------------------------
// Masked row softmax, TWO rows per CTA. 512 threads; each thread covers 16
// columns of row 2b AND row 2b+1. The s2 load at a column is SHARED by both
// rows (-25% load instructions), and the two rows' sums reduce through ONE
// barrier (-50% barriers/row). Phase 1 keeps 12 independent loads in flight
// per thread (deepest MLP yet). Shift C per row known at CTA start.
// ---------------------------------------------------------------------------
__global__ void __launch_bounds__(512, 2)
attn_kernel(const float* __restrict__ adj, float* __restrict__ out) {
    const int r0 = blockIdx.x * 2;
    const int r1 = r0 + 1;
    const float4* __restrict__ arowA = (const float4*)(adj + (size_t)r0 * N_NODES);
    const float4* __restrict__ arowB = (const float4*)(adj + (size_t)r1 * N_NODES);
    float4* __restrict__ orowA = (float4*)(out + (size_t)r0 * N_NODES);
    float4* __restrict__ orowB = (float4*)(out + (size_t)r1 * N_NODES);
    const float4* __restrict__ s2v = (const float4*)g_s2;

    const float s1A = g_s1[r0];
    const float s1B = g_s1[r1];
    const float s2max = dec_f32(g_s2max_u);
    float ctA = s1A + s2max, ctB = s1B + s2max;
    const float CA = (ctA >= 0.f) ? ctA : ALPHA * ctA;
    const float CB = (ctB >= 0.f) ? ctB : ALPHA * ctB;
    const int tid  = threadIdx.x;
    const int lane = tid & 31;
    const int wid  = tid >> 5;           // 0..15

    float eA[16], eB[16];

    // Phase 1: front-batched loads (adjA, adjB, shared s2) + masked lrelu.
    #pragma unroll
    for (int c = 0; c < 4; c++) {
        int idx = c * 512 + tid;          // float4 index within row
        float4 a4 = arowA[idx];
        float4 b4 = arowB[idx];
        float4 s4 = s2v[idx];
        float xA0 = s1A + s4.x; xA0 = (xA0 >= 0.f) ? xA0 : ALPHA * xA0;
        float xA1 = s1A + s4.y; xA1 = (xA1 >= 0.f) ? xA1 : ALPHA * xA1;
        float xA2 = s1A + s4.z; xA2 = (xA2 >= 0.f) ? xA2 : ALPHA * xA2;
        float xA3 = s1A + s4.w; xA3 = (xA3 >= 0.f) ? xA3 : ALPHA * xA3;
        float xB0 = s1B + s4.x; xB0 = (xB0 >= 0.f) ? xB0 : ALPHA * xB0;
        float xB1 = s1B + s4.y; xB1 = (xB1 >= 0.f) ? xB1 : ALPHA * xB1;
        float xB2 = s1B + s4.z; xB2 = (xB2 >= 0.f) ? xB2 : ALPHA * xB2;
        float xB3 = s1B + s4.w; xB3 = (xB3 >= 0.f) ? xB3 : ALPHA * xB3;
        eA[c * 4 + 0] = (a4.x >= 0.5f) ? xA0 : -CUDART_INF_F;
        eA[c * 4 + 1] = (a4.y >= 0.5f) ? xA1 : -CUDART_INF_F;
        eA[c * 4 + 2] = (a4.z >= 0.5f) ? xA2 : -CUDART_INF_F;
        eA[c * 4 + 3] = (a4.w >= 0.5f) ? xA3 : -CUDART_INF_F;
        eB[c * 4 + 0] = (b4.x >= 0.5f) ? xB0 : -CUDART_INF_F;
        eB[c * 4 + 1] = (b4.y >= 0.5f) ? xB1 : -CUDART_INF_F;
        eB[c * 4 + 2] = (b4.z >= 0.5f) ? xB2 : -CUDART_INF_F;
        eB[c * 4 + 3] = (b4.w >= 0.5f) ? xB3 : -CUDART_INF_F;
    }

    // Phase 2: exponentiate both rows (registers only), accumulate sums.
    float lsA = 0.f, lsB = 0.f;
    #pragma unroll
    for (int i = 0; i < 16; i++) {
        float pA = __expf(eA[i] - CA);   // exp(-inf) -> 0 for masked entries
        float pB = __expf(eB[i] - CB);
        eA[i] = pA;
        eB[i] = pB;
        lsA += pA;
        lsB += pB;
    }

    // Block-reduce both sums through ONE barrier (16 warps).
    __shared__ float smA[16], smB[16];
    #pragma unroll
    for (int off = 16; off; off >>= 1) {
        lsA += __shfl_xor_sync(0xffffffffu, lsA, off);
        lsB += __shfl_xor_sync(0xffffffffu, lsB, off);
    }
    if (lane == 0) { smA[wid] = lsA; smB[wid] = lsB; }
    __syncthreads();
    float rsA = smA[0], rsB = smB[0];
    #pragma unroll
    for (int w = 1; w < 16; w++) { rsA += smA[w]; rsB += smB[w]; }
    float invA = 1.f / rsA;
    float invB = 1.f / rsB;

    // Phase 3: normalize + write both rows.
    #pragma unroll
    for (int c = 0; c < 4; c++) {
        int idx = c * 512 + tid;
        float4 oA, oB;
        oA.x = eA[c * 4 + 0] * invA;
        oA.y = eA[c * 4 + 1] * invA;
        oA.z = eA[c * 4 + 2] * invA;
        oA.w = eA[c * 4 + 3] * invA;
        oB.x = eB[c * 4 + 0] * invB;
        oB.y = eB[c * 4 + 1] * invB;
        oB.z = eB[c * 4 + 2] * invB;
        oB.w = eB[c * 4 + 3] * invB;
        orowA[idx] = oA;
        orowB[idx] = oB;
    }
}

// ---------------------------------------------------------------------------
extern "C" void kernel_launch(void* const* d_in, const int* in_sizes, int n_in,
                              void* d_out, int out_size) {
    const float* nodes = (const float*)d_in[0];   // [8192, 512]
    const float* adj   = (const float*)d_in[1];   // [8192, 8192]
    const float* W     = (const float*)d_in[2];   // [512, 512]
    const float* a     = (const float*)d_in[3];   // [1024]
    float* out = (float*)d_out;                   // [8192, 8192]

    wvec_part_kernel<<<NPART, 256>>>(W, a);
    wvec_reduce_kernel<<<2, 1024>>>();
    sdot_kernel<<<N_NODES / 8, 256>>>(nodes);     // 8 warps/block, 1 warp/row
    attn_kernel<<<N_NODES / 2, 512>>>(adj, out);  // 2 rows per CTA
}